// round 15
// baseline (speedup 1.0000x reference)
#include <cuda_runtime.h>

// SPNBP compute_quant_to_alphabet — warp-decoupled scatter, atomic (no-RMW)
// accumulation into per-warp private buffers.
//
// out[n,b] = T[b+1] - T[b],  T[j] = sum_k w_k * e_j^k,
//   e_0 = 0, e_256 = 1, e_j = Phi(basec_k + (j-128)*inv_k) (increasing in j).
//
// Phi (A&S 26.2.17, pdf constant folded) saturates EXACTLY in fp32 at
// |x| >= 5.5. Decompose T = A + prefix(m):
//   A[j]    += w_k * Phi(cc_j)  for active edges j in [jlo_k, jsat_k) (<= ~22)
//   m[jsat] += w_k              (Phi == 1 for all j >= jsat)
// prefix cancels in the diff: out[b] = A[b+1] - A[b] + m[b+1].
//
// One block per n (grid 1024 = single wave at 256 thr), 8 warps, each fully
// self-contained until the final reduce (one __syncthreads total). Scatter
// updates use smem atomicAdd into the warp's PRIVATE accumulator: atomics
// are fire-and-forget (no return dependency), so the 8 unrolled passes have
// NO cross-pass LDS ordering chain (the RMW-alias serialization of R13) and
// cost 1 issue slot per update instead of 3. Zero contention: addresses are
// contiguous-distinct within a pass, array is warp-private.

#define NBINS 256
#define KMAX  64
#define NW    8
#define TPB   (NW * 32)
#define ASZ   260                  // per-array stride (256+pad)

__device__ __forceinline__ float phi_fast(float x)
{
    const float ax = fabsf(x);
    const float t  = __frcp_rn(fmaf(0.2316419f, ax, 1.0f));
    // A&S 26.2.17 coefficients pre-scaled by 1/sqrt(2*pi)
    float p = fmaf(0.53070271f, t, -0.72657598f);
    p = fmaf(p, t,  0.71070688f);
    p = fmaf(p, t, -0.14224835f);
    p = fmaf(p, t,  0.12741479f);
    p = p * t;
    const float e = exp2f(-0.72134752f * ax * ax);   // log2(e)/2 folded
    const float y = fmaf(-e, p, 1.0f);               // Phi(|x|); ==1 for ax>=5.5
    return (x >= 0.0f) ? y : (1.0f - y);
}

__global__ __launch_bounds__(TPB)
void spnbp_kernel(const float* __restrict__ Q,
                  const float* __restrict__ Q0,
                  const float* __restrict__ base_mean,
                  const float* __restrict__ base_var,
                  const float* __restrict__ mix_p,
                  float* __restrict__ out,
                  int N, int K)
{
    const int n    = blockIdx.x;
    const int tid  = threadIdx.x;
    const int warp = tid >> 5;
    const int lane = tid & 31;

    __shared__ alignas(16) float  s_A[NW][ASZ];      // per-warp edge sums
    __shared__ alignas(16) float  s_M[NW][ASZ];      // per-warp markers
    __shared__ alignas(16) float4 s_kc[NW][NW];      // staged per-k constants

    // ---- per-warp zeroing of own arrays (no cross-warp ordering) ----
    {
        float4* zA = (float4*)&s_A[warp][0];         // ASZ/4 = 65 float4 each
        float4* zM = (float4*)&s_M[warp][0];
        #pragma unroll
        for (int i = lane; i < ASZ / 4; i += 32) {
            zA[i] = make_float4(0.f, 0.f, 0.f, 0.f);
            zM[i] = make_float4(0.f, 0.f, 0.f, 0.f);
        }
        if (lane == 0) {
            zA[ASZ / 4 - 1] = make_float4(0.f, 0.f, 0.f, 0.f);
            zM[ASZ / 4 - 1] = make_float4(0.f, 0.f, 0.f, 0.f);
        }
    }

    // ---- lanes 0-7: constants for this warp's 8 k's (k = warp + 8*lane) ----
    if (lane < NW) {
        const int k = warp + (lane << 3);
        float basec = 0.0f, inv = 1.0f, w = 0.0f;
        int   jlo = 1, jsat = 1;
        if (k < K) {
            const float qd  = Q[(size_t)n * N + n];    // diag(Q)[n]
            const float q0  = Q0[n];
            const float bm  = base_mean[k * N + n];
            const float bv  = base_var [k * N + n];
            w   = mix_p[k * N + n];
            inv = rsqrtf(qd * qd * bv);
            basec = (-qd * bm - q0) * inv;
            const float rinv = __frcp_rn(inv);
            // cc crosses -5.5 at tlo, +5.5 at thi (cc increasing in j)
            const float tlo = fmaf(-5.5f - basec, rinv, 128.0f);
            const float thi = fmaf( 5.5f - basec, rinv, 128.0f);
            // j < jlo: Phi exact 0 (incl. forced e_0); j >= jsat: Phi exact 1
            // (incl. forced e_256)
            jlo  = __float2int_rd(fminf(fmaxf(tlo, 1.0f), 256.0f));
            jsat = __float2int_ru(fminf(fmaxf(thi, 0.0f), 256.0f));
            if (jsat < jlo) jsat = jlo;
        }
        s_kc[warp][lane] = make_float4(basec, inv, w,
                                       __int_as_float(jlo | ((jsat - jlo) << 16)));
        atomicAdd(&s_M[warp][jsat], w);        // marker: step mass at jsat
    }
    __syncwarp();

    // ---- 8 fully-unrolled scatter passes: fire-and-forget atomics ----
    {
        float* __restrict__ acc = &s_A[warp][0];
        bool wide = false;
        #pragma unroll
        for (int p = 0; p < NW; ++p) {
            const float4 c   = s_kc[warp][p];           // LDS.128 broadcast
            const int    pk  = __float_as_int(c.w);
            const int    jlo = pk & 0xffff;
            const int    nE  = pk >> 16;                // <= ~22 here
            if (lane < nE) {
                const float cc = fmaf((float)(jlo + lane - 128), c.y, c.x);
                atomicAdd(&acc[jlo + lane], c.z * phi_fast(cc));
            }
            wide |= (nE > 32);
        }
        if (__any_sync(0xffffffffu, wide)) {            // cold, never taken here
            #pragma unroll 1
            for (int p = 0; p < NW; ++p) {
                const float4 c   = s_kc[warp][p];
                const int    pk  = __float_as_int(c.w);
                const int    jlo = pk & 0xffff;
                const int    nE  = pk >> 16;
                for (int i = 32 + lane; i < nE; i += 32) {
                    const float cc = fmaf((float)(jlo + i - 128), c.y, c.x);
                    atomicAdd(&acc[jlo + i], c.z * phi_fast(cc));
                }
            }
        }
    }
    __syncthreads();                                    // the only block barrier

    // ---- reduce + diff + coalesced store ----
    {
        float d = 0.0f;
        #pragma unroll
        for (int i = 0; i < NW; ++i)
            d += s_A[i][tid + 1] - s_A[i][tid]          // A[0]=A[256]=0 by constr.
               + s_M[i][tid + 1];                       // markers
        out[(size_t)n * NBINS + tid] = d;
    }
}

extern "C" void kernel_launch(void* const* d_in, const int* in_sizes, int n_in,
                              void* d_out, int out_size)
{
    const float* Q     = (const float*)d_in[0];   // [N, N]
    const float* Q0    = (const float*)d_in[1];   // [N, 1]
    const float* bmean = (const float*)d_in[2];   // [K, N]
    const float* bvar  = (const float*)d_in[3];   // [K, N]
    const float* mp    = (const float*)d_in[4];   // [K, N, 1]
    float* out = (float*)d_out;                   // [N, 256]

    const int N = in_sizes[1];                    // 1024
    const int K = in_sizes[2] / N;                // 64

    spnbp_kernel<<<N, TPB>>>(Q, Q0, bmean, bvar, mp, out, N, K);
}

// round 16
// speedup vs baseline: 1.0597x; 1.0597x over previous
#include <cuda_runtime.h>

// SPNBP compute_quant_to_alphabet — warp-decoupled scatter + markers,
// approx-rcp Phi, prologue-hoisted edge affine, early LDG issue.
//
// out[n,b] = T[b+1] - T[b],  T[j] = sum_k w_k * e_j^k,
//   e_0 = 0, e_256 = 1, e_j = Phi(basec_k + (j-128)*inv_k) (increasing in j).
//
// Phi (A&S 26.2.17, pdf constant folded) saturates EXACTLY in fp32 at
// |x| >= 5.5 (margin 2x even with rcp.approx). Decompose T = A + prefix(m):
//   A[j]    += w_k * Phi(cc_j)  for active edges j in [jlo_k, jsat_k) (<= ~22)
//   m[jsat] += w_k              (Phi == 1 for all j >= jsat)
// prefix cancels in the diff: out[b] = A[b+1] - A[b] + m[b+1].
//
// One block per n (grid 1024 = single wave at 256 thr), 8 warps, each fully
// self-contained until the final reduce (one __syncthreads). Per warp:
// LDGs issued FIRST (latency hidden behind zeroing), constants staged in
// smem incl. pre-shifted basec' = basec + (jlo-128)*inv, then 8 unrolled
// scatter passes with cc = fma(lane, inv, basec') and conflict-free RMW.

#define NBINS 256
#define KMAX  64
#define NW    8
#define TPB   (NW * 32)
#define ASZ   260                  // per-array stride (256+pad)

__device__ __forceinline__ float rcp_approx(float x)
{
    float r;
    asm("rcp.approx.f32 %0, %1;" : "=f"(r) : "f"(x));
    return r;
}

__device__ __forceinline__ float phi_fast(float x)
{
    const float ax = fabsf(x);
    const float t  = rcp_approx(fmaf(0.2316419f, ax, 1.0f));   // MUFU.RCP only
    // A&S 26.2.17 coefficients pre-scaled by 1/sqrt(2*pi)
    float p = fmaf(0.53070271f, t, -0.72657598f);
    p = fmaf(p, t,  0.71070688f);
    p = fmaf(p, t, -0.14224835f);
    p = fmaf(p, t,  0.12741479f);
    p = p * t;
    const float e = exp2f(-0.72134752f * x * x);     // sign-free, log2(e)/2 folded
    const float y = fmaf(-e, p, 1.0f);               // Phi(|x|); ==1 for ax>=5.5
    return (x >= 0.0f) ? y : (1.0f - y);
}

__global__ __launch_bounds__(TPB)
void spnbp_kernel(const float* __restrict__ Q,
                  const float* __restrict__ Q0,
                  const float* __restrict__ base_mean,
                  const float* __restrict__ base_var,
                  const float* __restrict__ mix_p,
                  float* __restrict__ out,
                  int N, int K)
{
    const int n    = blockIdx.x;
    const int tid  = threadIdx.x;
    const int warp = tid >> 5;
    const int lane = tid & 31;

    // per-warp: [0] = A (edge sums), [1] = M (saturation markers)
    __shared__ alignas(16) float  s_AM[NW][2][ASZ];
    __shared__ alignas(16) float4 s_kc[NW][NW];      // staged per-k constants

    // ---- issue prologue loads FIRST (latency overlaps zeroing below) ----
    const int k = warp + (lane << 3);                // this lane's k (lane<8)
    float bm = 0.0f, bv = 1.0f, w = 0.0f, qd = 1.0f, q0 = 0.0f;
    if (lane < NW && k < K) {
        bm = base_mean[k * N + n];
        bv = base_var [k * N + n];
        w  = mix_p[k * N + n];
        qd = Q[(size_t)n * N + n];                   // diag(Q)[n]
        q0 = Q0[n];
    }

    // ---- per-warp zeroing of own arrays (no cross-warp ordering) ----
    {
        float4* z = (float4*)&s_AM[warp][0][0];      // 2*ASZ/4 = 130 float4
        #pragma unroll
        for (int i = lane; i < 2 * ASZ / 4; i += 32)
            z[i] = make_float4(0.f, 0.f, 0.f, 0.f);
    }

    // ---- lanes 0-7: window constants for this warp's 8 k's ----
    if (lane < NW) {
        float basec = 0.0f, inv = 1.0f, ww = 0.0f;
        int   jlo = 1, jsat = 1;
        if (k < K) {
            ww  = w;
            inv = rsqrtf(qd * qd * bv);
            basec = (-qd * bm - q0) * inv;
            const float rinv = rcp_approx(inv);
            // cc crosses -5.5 at tlo, +5.5 at thi (cc increasing in j)
            const float tlo = fmaf(-5.5f - basec, rinv, 128.0f);
            const float thi = fmaf( 5.5f - basec, rinv, 128.0f);
            // j < jlo: Phi exact 0 (incl. forced e_0); j >= jsat: Phi exact 1
            // (incl. forced e_256)
            jlo  = __float2int_rd(fminf(fmaxf(tlo, 1.0f), 256.0f));
            jsat = __float2int_ru(fminf(fmaxf(thi, 0.0f), 256.0f));
            if (jsat < jlo) jsat = jlo;
        }
        // pre-shift: cc at edge (jlo+lane) = fma(lane, inv, basec')
        const float basec2 = fmaf((float)(jlo - 128), inv, basec);
        s_kc[warp][lane] = make_float4(basec2, inv, ww,
                                       __int_as_float(jlo | ((jsat - jlo) << 16)));
        atomicAdd(&s_AM[warp][1][jsat], ww);   // marker: step mass at jsat
    }
    __syncwarp();

    // ---- 8 fully-unrolled scatter passes into this warp's accumulator ----
    {
        float* __restrict__ acc = &s_AM[warp][0][0];
        const float lanef = (float)lane;
        #pragma unroll
        for (int p = 0; p < NW; ++p) {
            const float4 c   = s_kc[warp][p];           // LDS.128 broadcast
            const int    pk  = __float_as_int(c.w);
            const int    jlo = pk & 0xffff;
            const int    nE  = pk >> 16;                // <= ~22 here
            if (lane < nE) {
                const float cc = fmaf(lanef, c.y, c.x);
                acc[jlo + lane] += c.z * phi_fast(cc);  // conflict-free RMW
            }
            if (nE > 32) {                              // cold, never taken here
                for (int i = 32 + lane; i < nE; i += 32) {
                    const float cc = fmaf((float)i, c.y, c.x);
                    acc[jlo + i] += c.z * phi_fast(cc);
                }
            }
        }
    }
    __syncthreads();                                    // the only block barrier

    // ---- reduce + diff + coalesced store ----
    {
        float d = 0.0f;
        #pragma unroll
        for (int i = 0; i < NW; ++i)
            d += s_AM[i][0][tid + 1] - s_AM[i][0][tid]  // A[0]=A[256]=0 by constr.
               + s_AM[i][1][tid + 1];                   // markers
        out[(size_t)n * NBINS + tid] = d;
    }
}

extern "C" void kernel_launch(void* const* d_in, const int* in_sizes, int n_in,
                              void* d_out, int out_size)
{
    const float* Q     = (const float*)d_in[0];   // [N, N]
    const float* Q0    = (const float*)d_in[1];   // [N, 1]
    const float* bmean = (const float*)d_in[2];   // [K, N]
    const float* bvar  = (const float*)d_in[3];   // [K, N]
    const float* mp    = (const float*)d_in[4];   // [K, N, 1]
    float* out = (float*)d_out;                   // [N, 256]

    const int N = in_sizes[1];                    // 1024
    const int K = in_sizes[2] / N;                // 64

    spnbp_kernel<<<N, TPB>>>(Q, Q0, bmean, bvar, mp, out, N, K);
}